// round 15
// baseline (speedup 1.0000x reference)
#include <cuda_runtime.h>
#include <math.h>
#include <stdint.h>

#define NLAYER 12
#define NH 12
#define DH 64
#define DMODEL 768
#define DFF 3072
#define NV 10000
#define QLEN 512
#define MLEN 512
#define CLEN 32
#define BSZ 4
#define KLEN 1056
#define QB (QLEN*BSZ)
#define KB (KLEN*BSZ)
#define TND (3*NH*DH)
#define ND (NH*DH)
#define NBATCH (BSZ*NH)
#define TUSH 8192

#if defined(__CUDA_ARCH_FEAT_SM103_ALL) || defined(__CUDA_ARCH_FEAT_SM100_ALL)
#define HAS_TC 1
#else
#define HAS_TC 0
#endif

// ---------------- fp32 scratch ----------------
__device__ float g_h[QB*DMODEL];
__device__ float g_r[KLEN*DMODEL];
__device__ float g_heads[(size_t)KB*TND];
__device__ float g_rk[KLEN*DMODEL];
__device__ float g_ac[(size_t)NBATCH*QLEN*KLEN];
__device__ float g_bd[(size_t)NBATCH*QLEN*KLEN];
__device__ float g_av[QB*DMODEL];
__device__ float g_ff[(size_t)QB*DMODEL];
// ---------------- tiled bf16 hi/lo scratch ----------------
#define DECL(name, n) __device__ __align__(16) unsigned short name##_h[(size_t)(n)], name##_l[(size_t)(n)]
DECL(g_qkvT, (size_t)NLAYER*18*12*TUSH);
DECL(g_rnT,  (size_t)NLAYER*6*12*TUSH);
DECL(g_oT,   (size_t)NLAYER*6*12*TUSH);
DECL(g_w1T,  (size_t)NLAYER*24*12*TUSH);
DECL(g_w2T,  (size_t)NLAYER*6*48*TUSH);
DECL(g_pT,   (size_t)80*12*TUSH);
DECL(g_ktT,  (size_t)NBATCH*9*TUSH);
DECL(g_rkT,  (size_t)12*9*TUSH);
DECL(g_vT,   (size_t)NBATCH*17*TUSH);
DECL(g_prT,  (size_t)NBATCH*4*17*TUSH);
DECL(g_qA0,  (size_t)NBATCH*4*TUSH);
DECL(g_qA1,  (size_t)NBATCH*4*TUSH);
DECL(g_hA,   (size_t)16*12*TUSH);
DECL(g_mA,   (size_t)16*12*TUSH);
DECL(g_cA,   (size_t)12*TUSH);
DECL(g_rA,   (size_t)9*12*TUSH);
DECL(g_avA,  (size_t)16*12*TUSH);
DECL(g_ffA,  (size_t)16*48*TUSH);
#undef DECL

// ---------------- PTX helpers ----------------
__device__ __forceinline__ uint32_t smem_u32(const void* p) {
    uint32_t a;
    asm("{ .reg .u64 t; cvta.to.shared.u64 t, %1; cvt.u32.u64 %0, t; }" : "=r"(a) : "l"(p));
    return a;
}
#define MBAR_INIT(a,c) asm volatile("mbarrier.init.shared.b64 [%0], %1;" :: "r"((uint32_t)(a)), "r"((uint32_t)(c)) : "memory")
#define MBAR_INVAL(a)  asm volatile("mbarrier.inval.shared.b64 [%0];" :: "r"((uint32_t)(a)) : "memory")
#define MBAR_EXPECT(a,b) asm volatile("mbarrier.arrive.expect_tx.shared.b64 _, [%0], %1;" :: "r"((uint32_t)(a)), "r"((uint32_t)(b)) : "memory")
#define MBAR_WAIT(a,p) do { uint32_t _m=(uint32_t)(a), _p=(uint32_t)(p); \
    asm volatile("{\n\t.reg .pred P1;\n\tWL_%=:\n\t" \
        "mbarrier.try_wait.parity.acquire.cta.shared::cta.b64 P1, [%0], %1, 0x989680;\n\t" \
        "@P1 bra.uni WD_%=;\n\tbra.uni WL_%=;\n\tWD_%=:\n\t}" :: "r"(_m), "r"(_p) : "memory"); } while(0)
#define BULK(dst, src, bytes, mbar) \
    asm volatile("cp.async.bulk.shared::cluster.global.mbarrier::complete_tx::bytes [%0], [%1], %2, [%3];" \
        :: "r"((uint32_t)(dst)), "l"(src), "r"((uint32_t)(bytes)), "r"((uint32_t)(mbar)) : "memory")
#define TC_ALLOC(a,n)   asm volatile("tcgen05.alloc.cta_group::1.sync.aligned.shared::cta.b32 [%0], %1;" :: "r"((uint32_t)(a)), "r"((uint32_t)(n)) : "memory")
#define TC_DEALLOC(t,n) asm volatile("tcgen05.dealloc.cta_group::1.sync.aligned.b32 %0, %1;" :: "r"(t), "r"((uint32_t)(n)))
#define TC_RELINQ()     asm volatile("tcgen05.relinquish_alloc_permit.cta_group::1.sync.aligned;")
#define TC_COMMIT(a)    asm volatile("tcgen05.commit.cta_group::1.mbarrier::arrive::one.shared::cluster.b64 [%0];" :: "r"((uint32_t)(a)) : "memory")
#define TC_WAIT_LD()    asm volatile("tcgen05.wait::ld.sync.aligned;" ::: "memory")
#define TC_FENCE_AFT()  asm volatile("tcgen05.fence::after_thread_sync;" ::: "memory")
#define TC_LD_X32(r, ta) asm volatile( \
    "tcgen05.ld.sync.aligned.32x32b.x32.b32 " \
    "{%0,%1,%2,%3,%4,%5,%6,%7,%8,%9,%10,%11,%12,%13,%14,%15," \
    "%16,%17,%18,%19,%20,%21,%22,%23,%24,%25,%26,%27,%28,%29,%30,%31}, [%32];" \
    : "=r"((r)[0]),"=r"((r)[1]),"=r"((r)[2]),"=r"((r)[3]),"=r"((r)[4]),"=r"((r)[5]),"=r"((r)[6]),"=r"((r)[7]), \
      "=r"((r)[8]),"=r"((r)[9]),"=r"((r)[10]),"=r"((r)[11]),"=r"((r)[12]),"=r"((r)[13]),"=r"((r)[14]),"=r"((r)[15]), \
      "=r"((r)[16]),"=r"((r)[17]),"=r"((r)[18]),"=r"((r)[19]),"=r"((r)[20]),"=r"((r)[21]),"=r"((r)[22]),"=r"((r)[23]), \
      "=r"((r)[24]),"=r"((r)[25]),"=r"((r)[26]),"=r"((r)[27]),"=r"((r)[28]),"=r"((r)[29]),"=r"((r)[30]),"=r"((r)[31]) \
    : "r"(ta))

static constexpr uint64_t DESC_BASE =
    (uint64_t(2) << 61) | (uint64_t(1) << 46) | (uint64_t(64) << 32) | (uint64_t(1) << 16);
#define MK_DESC(a) (DESC_BASE | ((uint64_t)((a) >> 4) & 0x3FFF))
#define IDESC_N128 0x8200490u
#define IDESC_N64  0x8100490u

#if HAS_TC
__device__ __forceinline__ void mma_bf16(uint32_t d, uint64_t ad, uint64_t bd,
                                         uint32_t idesc, uint32_t en) {
    asm volatile(
        "{\n\t.reg .pred p;\n\tsetp.ne.u32 p, %4, 0;\n\t"
        "tcgen05.mma.cta_group::1.kind::f16 [%0], %1, %2, %3, {%5, %5, %5, %5}, p;\n\t}"
        :: "r"(d), "l"(ad), "l"(bd), "r"(idesc), "r"(en), "r"(0u) : "memory");
}
#endif

__device__ __forceinline__ void split1(float x, unsigned short& h, unsigned short& l) {
    unsigned u = __float_as_uint(x);
    unsigned r = (u + 0x7fffu + ((u >> 16) & 1u)) & 0xffff0000u;
    h = (unsigned short)(r >> 16);
    unsigned v = __float_as_uint(x - __uint_as_float(r));
    l = (unsigned short)((v + 0x7fffu + ((v >> 16) & 1u)) >> 16);
}
__device__ __forceinline__ float bfpair(unsigned short h, unsigned short l) {
    return __uint_as_float((unsigned)h << 16) + __uint_as_float((unsigned)l << 16);
}
__device__ __forceinline__ float tread_f(const unsigned short* Hh, const unsigned short* Hl,
                                         long zoff, int kts, int r, int c) {
    long tile = (long)(r >> 7) * kts + (c >> 6);
    uint32_t bo = ((uint32_t)(r & 127) << 7) | ((uint32_t)(c & 63) << 1);
    bo ^= (bo >> 3) & 0x70;
    long o = zoff + tile * TUSH + (bo >> 1);
    float hv = __uint_as_float((unsigned)Hh[o] << 16);
    return Hl ? hv + __uint_as_float((unsigned)Hl[o] << 16) : hv;
}
__device__ __forceinline__ void twrite(unsigned short* Dh, unsigned short* Dl,
                                       int kts, int r, int c, float v) {
    long tile = (long)(r >> 7) * kts + (c >> 6);
    uint32_t bo = ((uint32_t)(r & 127) << 7) | ((uint32_t)(c & 63) << 1);
    bo ^= (bo >> 3) & 0x70;
    long o = tile * TUSH + (bo >> 1);
    unsigned short h, l;
    split1(v, h, l);
    Dh[o] = h; Dl[o] = l;
}

__device__ __forceinline__ float warp_sum(float v) {
    #pragma unroll
    for (int o = 16; o; o >>= 1) v += __shfl_xor_sync(0xffffffffu, v, o);
    return v;
}
__device__ __forceinline__ float warp_max(float v) {
    #pragma unroll
    for (int o = 16; o; o >>= 1) v = fmaxf(v, __shfl_xor_sync(0xffffffffu, v, o));
    return v;
}
__device__ __forceinline__ float block_sum(float v, float* red) {
    v = warp_sum(v);
    __syncthreads();
    if ((threadIdx.x & 31) == 0) red[threadIdx.x >> 5] = v;
    __syncthreads();
    float r = 0.f;
    #pragma unroll
    for (int k = 0; k < 8; k++) r += red[k];
    return r;
}

// ---------------- elementwise ----------------
__global__ void embed_kernel(const int* __restrict__ x, const float* __restrict__ emb) {
    int idx = blockIdx.x * 256 + threadIdx.x;
    if (idx >= QB * DMODEL) return;
    int row = idx / DMODEL, d = idx % DMODEL;
    float v = emb[(size_t)x[row] * DMODEL + d] * sqrtf(768.0f);
    g_h[idx] = v;
    twrite(g_hA_h, g_hA_l, 12, row, d, v);
}
__global__ void posemb_kernel() {
    int idx = blockIdx.x * 256 + threadIdx.x;
    if (idx >= KLEN * DMODEL) return;
    int p = idx / DMODEL, d = idx % DMODEL;
    float pos = (float)(KLEN - 1 - p);
    int dd = (d < 384) ? d : d - 384;
    float s = pos / powf(10000.0f, (float)(2 * dd) / 768.0f);
    g_r[idx] = (d < 384) ? sinf(s) : cosf(s);
}

// ---- pack (no transpose) ----
__global__ void __launch_bounds__(256)
pack_nT(const float* __restrict__ src, int lds, int zq, long offB, long offN,
        int rowsN, int colsK, const float* __restrict__ bias,
        unsigned short* __restrict__ dh, unsigned short* __restrict__ dl,
        int kts, long zStr)
{
    int z = blockIdx.z, bb = z / zq, nn = z % zq;
    const float* s = src + (long)bb * offB + (long)nn * offN;
    const float* bi = bias ? (bias + (long)nn * DH) : (const float*)0;
    long dbase = (long)z * zStr + ((long)blockIdx.x * kts + blockIdx.y) * TUSH;
    int n0 = blockIdx.x << 7, k0 = blockIdx.y << 6;
    #pragma unroll
    for (int g = 0; g < 4; g++) {
        int gi = threadIdx.x + g * 256;
        int n = gi >> 3, kg = gi & 7;
        int r = n0 + n, c = k0 + kg * 8;
        float xv[8] = {0,0,0,0,0,0,0,0};
        if (r < rowsN && c < colsK) {
            const float* p = s + (long)r * lds + c;
            float4 v0 = *(const float4*)p, v1 = *(const float4*)(p + 4);
            xv[0]=v0.x; xv[1]=v0.y; xv[2]=v0.z; xv[3]=v0.w;
            xv[4]=v1.x; xv[5]=v1.y; xv[6]=v1.z; xv[7]=v1.w;
            if (bi) {
                #pragma unroll
                for (int j = 0; j < 8; j++) xv[j] += bi[c + j];
            }
        }
        unsigned short h[8], l[8];
        #pragma unroll
        for (int j = 0; j < 8; j++) split1(xv[j], h[j], l[j]);
        uint32_t bo = ((uint32_t)n << 7) | ((uint32_t)kg << 4);
        uint32_t sw = bo ^ ((bo >> 3) & 0x70);
        *(uint4*)(dh + dbase + (sw >> 1)) = make_uint4(((unsigned)h[1]<<16)|h[0], ((unsigned)h[3]<<16)|h[2],
                                                       ((unsigned)h[5]<<16)|h[4], ((unsigned)h[7]<<16)|h[6]);
        *(uint4*)(dl + dbase + (sw >> 1)) = make_uint4(((unsigned)l[1]<<16)|l[0], ((unsigned)l[3]<<16)|l[2],
                                                       ((unsigned)l[5]<<16)|l[4], ((unsigned)l[7]<<16)|l[6]);
    }
}

// ---- pack with transpose ----
__global__ void __launch_bounds__(256)
pack_wT(const float* __restrict__ src, int lds, int zq, long offB, long offN,
        int srcRows, int srcCols,
        unsigned short* __restrict__ dh, unsigned short* __restrict__ dl,
        int kts, long zStr)
{
    __shared__ float t[64][129];
    int z = blockIdx.z, bb = z / zq, nn = z % zq;
    const float* s = src + (long)bb * offB + (long)nn * offN;
    long dbase = (long)z * zStr + ((long)blockIdx.x * kts + blockIdx.y) * TUSH;
    int n0 = blockIdx.x << 7, k0 = blockIdx.y << 6;
    #pragma unroll
    for (int i = 0; i < 32; i++) {
        int idx = threadIdx.x + i * 256;
        int kr = idx >> 7, nc = idx & 127;
        float v = 0.f;
        if (k0 + kr < srcRows && n0 + nc < srcCols)
            v = s[(long)(k0 + kr) * lds + n0 + nc];
        t[kr][nc] = v;
    }
    __syncthreads();
    #pragma unroll
    for (int g = 0; g < 4; g++) {
        int gi = threadIdx.x + g * 256;
        int n = gi >> 3, kg = gi & 7;
        unsigned short h[8], l[8];
        #pragma unroll
        for (int j = 0; j < 8; j++) split1(t[kg * 8 + j][n], h[j], l[j]);
        uint32_t bo = ((uint32_t)n << 7) | ((uint32_t)kg << 4);
        uint32_t sw = bo ^ ((bo >> 3) & 0x70);
        *(uint4*)(dh + dbase + (sw >> 1)) = make_uint4(((unsigned)h[1]<<16)|h[0], ((unsigned)h[3]<<16)|h[2],
                                                       ((unsigned)h[5]<<16)|h[4], ((unsigned)h[7]<<16)|h[6]);
        *(uint4*)(dl + dbase + (sw >> 1)) = make_uint4(((unsigned)l[1]<<16)|l[0], ((unsigned)l[3]<<16)|l[2],
                                                       ((unsigned)l[5]<<16)|l[4], ((unsigned)l[7]<<16)|l[6]);
    }
}

// ---------------- GEMM ----------------
// nt2=1: 256-wide N per CTA (two B tiles per A tile). Alo may be null (hi-only A).
// dbuf: double-buffered staging. Coh: tiled bf16 output. mode: 0/1/2 score skips.
#define GT_SMEM_SB (1024 + 128 * 132 * 4)
#define GT_SMEM_N1 (1024 + 2 * 65536)
#define GT_SMEM_N2 (1024 + 2 * 98304)
#define GT_SMEM_PV (1024 + 2 * 49152)

__global__ void __launch_bounds__(256)
gemm_tc(const unsigned short* __restrict__ Ahi, const unsigned short* __restrict__ Alo,
        long aZb, long aZn,
        const unsigned short* __restrict__ Bhi, const unsigned short* __restrict__ Blo,
        long bZb, long bZn,
        float* __restrict__ C, int ldc, long cZb, long cZn,
        unsigned short* __restrict__ Coh, unsigned short* __restrict__ Col, int coKts,
        int M, int N, int K,
        const float* __restrict__ cbias, int relu, int mode, int dbuf, int nt2)
{
    extern __shared__ char smem[];
    const int tid = threadIdx.x;
    const int bb = blockIdx.z / NH, nn = blockIdx.z % NH;
    const int row0 = blockIdx.y * 128;
    const int col0 = blockIdx.x * (nt2 ? 256 : 128);
    if (mode == 2 && col0 > row0 + (CLEN + MLEN + 127)) return;
    if (mode == 1 && col0 + 127 < (QLEN - 1) - (row0 + 127)) return;
    const long aoff = (long)bb * aZb + (long)nn * aZn;
    const long boff = (long)bb * bZb + (long)nn * bZn;
    float* Cz = C ? (C + (long)bb * cZb + (long)nn * cZn) : (float*)0;
    const int KT = (K + 63) >> 6;
    const int hasAl = (Alo != 0);

#if HAS_TC
    const uint32_t sb = smem_u32(smem);
    const int wid = tid >> 5, lane = tid & 31;
    const uint32_t idesc = (N <= 64) ? IDESC_N64 : IDESC_N128;
    const uint32_t aB = hasAl ? 32768u : 16384u;
    const uint32_t bufB = aB + (nt2 ? 65536u : 32768u);
    if (wid == 0) { TC_ALLOC(sb, nt2 ? 256 : 128); TC_RELINQ(); }
    if (tid == 0) {
        MBAR_INIT(sb + 16, 1); MBAR_INIT(sb + 24, 1);
        MBAR_INIT(sb + 32, 1); MBAR_INIT(sb + 40, 1);
    }
    __syncthreads();
    uint32_t tmem;
    asm volatile("ld.shared.b32 %0, [%1];" : "=r"(tmem) : "r"(sb));

    if (tid == 0) {
        const long aT0 = aoff + (long)(row0 >> 7) * KT * TUSH;
        const int bt = nt2 ? blockIdx.x * 2 : blockIdx.x;
        const long bT0 = boff + (long)bt * KT * TUSH;
        const long bT1 = boff + (long)(bt + 1) * KT * TUSH;
        int pf[2] = {0, 0}, pd[2] = {0, 0};
#define ISSUE(t, b) do { \
            uint32_t _fb = sb + 16 + (uint32_t)(b) * 16; \
            uint32_t _bs = sb + 1024 + (uint32_t)(b) * bufB; \
            MBAR_EXPECT(_fb, bufB); \
            BULK(_bs, Ahi + aT0 + (long)(t) * TUSH, 16384, _fb); \
            if (hasAl) BULK(_bs + 16384, Alo + aT0 + (long)(t) * TUSH, 16384, _fb); \
            BULK(_bs + aB,         Bhi + bT0 + (long)(t) * TUSH, 16384, _fb); \
            BULK(_bs + aB + 16384, Blo + bT0 + (long)(t) * TUSH, 16384, _fb); \
            if (nt2) { \
                BULK(_bs + aB + 32768, Bhi + bT1 + (long)(t) * TUSH, 16384, _fb); \
                BULK(_bs + aB + 49152, Blo + bT1 + (long)(t) * TUSH, 16384, _fb); \
            } \
        } while (0)
        ISSUE(0, 0);
        for (int t = 0; t < KT; t++) {
            const int buf = dbuf ? (t & 1) : 0;
            if (dbuf && t + 1 < KT) {
                int nb = (t + 1) & 1;
                if (t + 1 >= 2) { MBAR_WAIT(sb + 24 + (uint32_t)nb * 16, pd[nb] & 1); pd[nb]++; }
                ISSUE(t + 1, nb);
            }
            MBAR_WAIT(sb + 16 + (uint32_t)buf * 16, pf[buf] & 1); pf[buf]++;
            const uint32_t bs = sb + 1024 + (uint32_t)buf * bufB;
            uint64_t dAh = MK_DESC(bs);
            uint64_t dAl = MK_DESC(bs + 16384);
            uint64_t dB0h = MK_DESC(bs + aB);
            uint64_t dB0l = MK_DESC(bs + aB + 16384);
            uint64_t dB1h = MK_DESC(bs + aB + 32768);
            uint64_t dB1l = MK_DESC(bs + aB + 49152);
            #pragma unroll
            for (int ks = 0; ks < 4; ks++) {
                uint32_t en0 = (t > 0 || ks > 0) ? 1u : 0u;
                mma_bf16(tmem, dAh + ks*2, dB0h + ks*2, idesc, en0);
                mma_bf16(tmem, dAh + ks*2, dB0l + ks*2, idesc, 1u);
                if (hasAl) mma_bf16(tmem, dAl + ks*2, dB0h + ks*2, idesc, 1u);
                if (nt2) {
                    mma_bf16(tmem + 128, dAh + ks*2, dB1h + ks*2, idesc, en0);
                    mma_bf16(tmem + 128, dAh + ks*2, dB1l + ks*2, idesc, 1u);
                    if (hasAl) mma_bf16(tmem + 128, dAl + ks*2, dB1h + ks*2, idesc, 1u);
                }
            }
            TC_COMMIT(sb + 24 + (uint32_t)buf * 16);
            if (!dbuf && t + 1 < KT) {
                MBAR_WAIT(sb + 24, pd[0] & 1); pd[0]++;
                ISSUE(t + 1, 0);
            }
        }
        if (dbuf) {
            if (KT >= 2) {
                int b2 = (KT - 2) & 1;
                MBAR_WAIT(sb + 24 + (uint32_t)b2 * 16, pd[b2] & 1); pd[b2]++;
            }
            int b1 = (KT - 1) & 1;
            MBAR_WAIT(sb + 24 + (uint32_t)b1 * 16, pd[b1] & 1);
        } else {
            MBAR_WAIT(sb + 24, pd[0] & 1);
        }
#undef ISSUE
    }
    __syncthreads();
    TC_FENCE_AFT();

    // ---- epilogue per 128-col tile ----
    for (int ct = 0; ct <= nt2; ct++) {
        float* Cs = (float*)(smem + 1024);
        int col0e = col0 + ct * 128;
        int sub = wid & 3, ch = wid >> 2;
        int rl = sub * 32 + lane;
        #pragma unroll
        for (int half = 0; half < 2; half++) {
            uint32_t dr[32];
            TC_LD_X32(dr, tmem + (uint32_t)(ct * 128 + ch * 64 + half * 32));
            TC_WAIT_LD();
            #pragma unroll
            for (int c = 0; c < 32; c++)
                Cs[rl * 132 + ch * 64 + half * 32 + c] = __uint_as_float(dr[c]);
        }
        __syncthreads();
        if (Coh) {
            long tb = ((long)(row0 >> 7) * coKts + (col0e >> 6)) * TUSH;
            #pragma unroll
            for (int half = 0; half < 2; half++) {
                long dbase = tb + (long)half * TUSH;
                #pragma unroll
                for (int g = 0; g < 4; g++) {
                    int gi = tid + g * 256;
                    int n = gi >> 3, kg = gi & 7;
                    unsigned short h8[8], l8[8];
                    #pragma unroll
                    for (int j = 0; j < 8; j++) {
                        int c = half * 64 + kg * 8 + j;
                        int cg = col0e + c;
                        float v = 0.f;
                        if (row0 + n < M && cg < N) {
                            v = Cs[n * 132 + c];
                            if (cbias) v += cbias[cg];
                            if (relu) v = fmaxf(v, 0.f);
                        }
                        split1(v, h8[j], l8[j]);
                    }
                    uint32_t bo = ((uint32_t)n << 7) | ((uint32_t)kg << 4);
                    uint32_t sw = bo ^ ((bo >> 3) & 0x70);
                    *(uint4*)(Coh + dbase + (sw >> 1)) = make_uint4(((unsigned)h8[1]<<16)|h8[0], ((unsigned)h8[3]<<16)|h8[2],
                                                                    ((unsigned)h8[5]<<16)|h8[4], ((unsigned)h8[7]<<16)|h8[6]);
                    *(uint4*)(Col + dbase + (sw >> 1)) = make_uint4(((unsigned)l8[1]<<16)|l8[0], ((unsigned)l8[3]<<16)|l8[2],
                                                                    ((unsigned)l8[5]<<16)|l8[4], ((unsigned)l8[7]<<16)|l8[6]);
                }
            }
        } else {
            for (int i2 = tid; i2 < 128 * 32; i2 += 256) {
                int row = i2 >> 5, c4 = (i2 & 31) << 2;
                int r = row0 + row;
                if (r >= M) continue;
                int cg = col0e + c4;
                if (cg >= N) continue;
                float4 v = *(float4*)&Cs[row * 132 + c4];
                float vv[4] = {v.x, v.y, v.z, v.w};
                if (cg + 3 < N) {
                    if (cbias) {
                        vv[0] += cbias[cg]; vv[1] += cbias[cg+1];
                        vv[2] += cbias[cg+2]; vv[3] += cbias[cg+3];
                    }
                    if (relu) {
                        #pragma unroll
                        for (int j = 0; j < 4; j++) vv[j] = fmaxf(vv[j], 0.f);
                    }
                    *(float4*)&Cz[(long)r * ldc + cg] = make_float4(vv[0], vv[1], vv[2], vv[3]);
                } else {
                    #pragma unroll
                    for (int j = 0; j < 4; j++) {
                        int c = cg + j;
                        if (c < N) {
                            float w = vv[j];
                            if (cbias) w += cbias[c];
                            if (relu) w = fmaxf(w, 0.f);
                            Cz[(long)r * ldc + c] = w;
                        }
                    }
                }
            }
        }
        __syncthreads();
    }
    if (tid == 0) { MBAR_INVAL(sb + 16); MBAR_INVAL(sb + 24); MBAR_INVAL(sb + 32); MBAR_INVAL(sb + 40); }
    if (wid == 0) TC_DEALLOC(tmem, nt2 ? 256 : 128);
#else
    // ---------- SIMT fallback (handles nt2 via wider col loop) ----------
    float* As = (float*)smem;
    float* Bs = (float*)smem + 16 * 132;
    const int ty4 = (tid >> 4) << 2, tx4 = (tid & 15) << 2;
    for (int ct = 0; ct <= nt2; ct++) {
        int col0e = col0 + ct * 128;
        float acc[8][8] = {};
        for (int k0 = 0; k0 < K; k0 += 16) {
            #pragma unroll
            for (int s = 0; s < 2; s++) {
                int idx = tid + s * 256;
                int m = idx >> 2, kc = (idx & 3) << 2;
                #pragma unroll
                for (int j = 0; j < 4; j++) {
                    float v = 0.f;
                    if (row0 + m < M && k0 + kc + j < K)
                        v = tread_f(Ahi, Alo, aoff, KT, row0 + m, k0 + kc + j);
                    As[(kc + j) * 132 + m] = v;
                }
            }
            #pragma unroll
            for (int s = 0; s < 8; s++) {
                int idx = tid + s * 256;
                int n = idx >> 4, kk2 = idx & 15;
                float v = 0.f;
                if (col0e + n < N && k0 + kk2 < K)
                    v = tread_f(Bhi, Blo, boff, KT, col0e + n, k0 + kk2);
                Bs[kk2 * 128 + n] = v;
            }
            __syncthreads();
            #pragma unroll
            for (int k = 0; k < 16; k++) {
                float4 xa0 = *(const float4*)&As[k*132 + ty4];
                float4 xa1 = *(const float4*)&As[k*132 + ty4 + 64];
                float4 xb0 = *(const float4*)&Bs[k*128 + tx4];
                float4 xb1 = *(const float4*)&Bs[k*128 + tx4 + 64];
                float av8[8] = {xa0.x,xa0.y,xa0.z,xa0.w, xa1.x,xa1.y,xa1.z,xa1.w};
                float bv8[8] = {xb0.x,xb0.y,xb0.z,xb0.w, xb1.x,xb1.y,xb1.z,xb1.w};
                #pragma unroll
                for (int i = 0; i < 8; i++)
                    #pragma unroll
                    for (int j = 0; j < 8; j++) acc[i][j] += av8[i] * bv8[j];
            }
            __syncthreads();
        }
        #pragma unroll
        for (int i = 0; i < 8; i++) {
            int r = row0 + ty4 + ((i < 4) ? i : 60 + i);
            if (r >= M) continue;
            #pragma unroll
            for (int j = 0; j < 8; j++) {
                int cg = col0e + tx4 + ((j < 4) ? j : 60 + j);
                if (cg >= N) continue;
                float v = acc[i][j];
                if (cbias) v += cbias[cg];
                if (relu) v = fmaxf(v, 0.f);
                if (Coh) twrite(Coh, Col, coKts, r, cg, v);
                else Cz[(long)r * ldc + cg] = v;
            }
        }
        __syncthreads();
    }
#endif
}

// ---------------- softmax: rel-shift folded; probs out tiled bf16 (hi only) ----------------
__global__ void __launch_bounds__(256) softmax_kernel() {
    int i = blockIdx.x, z = blockIdx.y;
    size_t rbase = ((size_t)z * QLEN + i) * KLEN;
    const float* row = g_ac + rbase;
    const float* bdrow = g_bd + rbase;
    int jmax = i + CLEN + MLEN;
    __shared__ float s[KLEN];
    __shared__ float red[8];
    int tid = threadIdx.x;
    float lmax = -3.0e38f;
    for (int j = tid; j <= jmax; j += 256) {
        float v = (row[j] + bdrow[j + QLEN - 1 - i]) * 0.125f;
        s[j] = v;
        lmax = fmaxf(lmax, v);
    }
    lmax = warp_max(lmax);
    __syncthreads();
    if ((tid & 31) == 0) red[tid >> 5] = lmax;
    __syncthreads();
    float m = red[0];
    #pragma unroll
    for (int k = 1; k < 8; k++) m = fmaxf(m, red[k]);
    float lsum = 0.f;
    for (int j = tid; j <= jmax; j += 256) { float e = expf(s[j] - m); s[j] = e; lsum += e; }
    float inv = 1.0f / block_sum(lsum, red);
    __syncthreads();
    long zb = (long)z * (4 * 17 * TUSH) + ((long)(i >> 7) * 17) * TUSH;
    for (int j = tid; j < 17 * 64; j += 256) {
        float p = (j <= jmax && j < KLEN) ? s[j] * inv : 0.0f;
        unsigned u = __float_as_uint(p);
        unsigned short h = (unsigned short)((u + 0x7fffu + ((u >> 16) & 1u)) >> 16);
        uint32_t bo = ((uint32_t)(i & 127) << 7) | ((uint32_t)(j & 63) << 1);
        bo ^= (bo >> 3) & 0x70;
        g_prT_h[zb + (long)(j >> 6) * TUSH + (bo >> 1)] = h;
    }
}

// ---------------- h = LN(h+res); emits tiled bf16 hA ----------------
__global__ void __launch_bounds__(256)
add_ln_kernel(float* __restrict__ h, const float* __restrict__ res,
              const float* __restrict__ g, const float* __restrict__ b,
              unsigned short* __restrict__ dh, unsigned short* __restrict__ dl)
{
    __shared__ float red[8];
    int row = blockIdx.x, tid = threadIdx.x;
    size_t base = (size_t)row * DMODEL;
    float x0 = h[base + tid]       + res[base + tid];
    float x1 = h[base + tid + 256] + res[base + tid + 256];
    float x2 = h[base + tid + 512] + res[base + tid + 512];
    float mean = block_sum(x0 + x1 + x2, red) * (1.0f / 768.0f);
    float d0 = x0 - mean, d1 = x1 - mean, d2 = x2 - mean;
    float inv = rsqrtf(block_sum(d0*d0 + d1*d1 + d2*d2, red) * (1.0f / 768.0f) + 1e-5f);
    float y0 = d0 * inv * g[tid]       + b[tid];
    float y1 = d1 * inv * g[tid + 256] + b[tid + 256];
    float y2 = d2 * inv * g[tid + 512] + b[tid + 512];
    h[base + tid]       = y0;
    h[base + tid + 256] = y1;
    h[base + tid + 512] = y2;
    twrite(dh, dl, 12, row, tid,       y0);
    twrite(dh, dl, 12, row, tid + 256, y1);
    twrite(dh, dl, 12, row, tid + 512, y2);
}

// ---------------- host ----------------
extern "C" void kernel_launch(void* const* d_in, const int* in_sizes, int n_in,
                              void* d_out, int out_size)
{
    const int*   x         = (const int*)  d_in[0];
    const float* condition = (const float*)d_in[1];
    const float* mems      = (const float*)d_in[2];
    const float* emb       = (const float*)d_in[3];
    const float* qkv_w     = (const float*)d_in[4];
    const float* r_net_w   = (const float*)d_in[5];
    const float* o_w       = (const float*)d_in[6];
    const float* ln1_g     = (const float*)d_in[7];
    const float* ln1_b     = (const float*)d_in[8];
    const float* w1        = (const float*)d_in[9];
    const float* b1        = (const float*)d_in[10];
    const float* w2        = (const float*)d_in[11];
    const float* b2        = (const float*)d_in[12];
    const float* ln2_g     = (const float*)d_in[13];
    const float* ln2_b     = (const float*)d_in[14];
    const float* r_w_bias  = (const float*)d_in[15];
    const float* r_r_bias  = (const float*)d_in[16];
    const float* proj_w    = (const float*)d_in[17];
    const float* proj_b    = (const float*)d_in[18];
    float* out = (float*)d_out;

    cudaFuncSetAttribute(gemm_tc, cudaFuncAttributeMaxDynamicSharedMemorySize, GT_SMEM_N2);

    float *h, *r, *heads, *rk, *ac, *bd, *av, *ff;
    unsigned short *qkvTh,*qkvTl,*rnTh,*rnTl,*oTh,*oTl,*w1Th,*w1Tl,*w2Th,*w2Tl,*pTh,*pTl;
    unsigned short *ktTh,*ktTl,*rkTh,*rkTl,*vTh,*vTl,*prTh,*qA0h,*qA0l,*qA1h,*qA1l;
    unsigned short *hAh,*hAl,*mAh,*mAl,*cAh,*cAl,*rAh,*rAl,*avAh,*avAl,*ffAh,*ffAl;
#define SYM(p, s) cudaGetSymbolAddress((void**)&p, s)
    SYM(h,g_h); SYM(r,g_r); SYM(heads,g_heads); SYM(rk,g_rk); SYM(ac,g_ac); SYM(bd,g_bd);
    SYM(av,g_av); SYM(ff,g_ff);
    SYM(qkvTh,g_qkvT_h); SYM(qkvTl,g_qkvT_l); SYM(rnTh,g_rnT_h); SYM(rnTl,g_rnT_l);
    SYM(oTh,g_oT_h); SYM(oTl,g_oT_l); SYM(w1Th,g_w1T_h); SYM(w1Tl,g_w1T_l);
    SYM(w2Th,g_w2T_h); SYM(w2Tl,g_w2T_l); SYM(pTh,g_pT_h); SYM(pTl,g_pT_l);
    SYM(ktTh,g_ktT_h); SYM(ktTl,g_ktT_l); SYM(rkTh,g_rkT_h); SYM(rkTl,g_rkT_l);
    SYM(vTh,g_vT_h); SYM(vTl,g_vT_l); SYM(prTh,g_prT_h);
    SYM(qA0h,g_qA0_h); SYM(qA0l,g_qA0_l); SYM(qA1h,g_qA1_h); SYM(qA1l,g_qA1_l);
    SYM(hAh,g_hA_h); SYM(hAl,g_hA_l); SYM(mAh,g_mA_h); SYM(mAl,g_mA_l);
    SYM(cAh,g_cA_h); SYM(cAl,g_cA_l); SYM(rAh,g_rA_h); SYM(rAl,g_rA_l);
    SYM(avAh,g_avA_h); SYM(avAl,g_avA_l); SYM(ffAh,g_ffA_h); SYM(ffAl,g_ffA_l);
#undef SYM

    pack_wT<<<dim3(18,12,NLAYER),256>>>(qkv_w, TND, 1, (long)DMODEL*TND, 0, DMODEL, TND,
                                        qkvTh, qkvTl, 12, (long)18*12*TUSH);
    embed_kernel<<<(QB*DMODEL+255)/256, 256>>>(x, emb);
    posemb_kernel<<<(KLEN*DMODEL+255)/256, 256>>>();

    int first = 1;
    for (int l = 0; l < NLAYER; l++) {
        long wq = (long)l*18*12*TUSH;
        float* q = heads + (size_t)(CLEN+MLEN)*BSZ*TND;

        gemm_tc<<<dim3(9,16,1),256,GT_SMEM_N2>>>(hAh, hAl, 0,0, qkvTh+wq, qkvTl+wq, 0,0,   // captured
            q, TND, 0,0, 0,0,0, QB, TND, DMODEL, 0,0,0,1,1);
        if (first) {
            pack_wT<<<dim3(6,12,NLAYER),256>>>(r_net_w, ND, 1, (long)DMODEL*ND, 0, DMODEL, ND,
                                               rnTh, rnTl, 12, (long)6*12*TUSH);
            pack_wT<<<dim3(6,12,NLAYER),256>>>(o_w, DMODEL, 1, (long)ND*DMODEL, 0, ND, DMODEL,
                                               oTh, oTl, 12, (long)6*12*TUSH);
            pack_wT<<<dim3(24,12,NLAYER),256>>>(w1, DFF, 1, (long)DMODEL*DFF, 0, DMODEL, DFF,
                                                w1Th, w1Tl, 12, (long)24*12*TUSH);
            pack_wT<<<dim3(6,48,NLAYER),256>>>(w2, DMODEL, 1, (long)DFF*DMODEL, 0, DFF, DMODEL,
                                               w2Th, w2Tl, 48, (long)6*48*TUSH);
            pack_wT<<<dim3(79,12,1),256>>>(proj_w, NV, 1, 0,0, DMODEL, NV, pTh, pTl, 12, 0);
            pack_nT<<<dim3(1,12,1),256>>>(condition, DMODEL, 1, 0,0, CLEN*BSZ, DMODEL, 0, cAh, cAl, 12, 0);
            pack_nT<<<dim3(9,12,1),256>>>(r, DMODEL, 1, 0,0, KLEN, DMODEL, 0, rAh, rAl, 12, 0);
            first = 0;
        }
        pack_nT<<<dim3(16,12,1),256>>>(mems + (size_t)l*MLEN*BSZ*DMODEL, DMODEL, 1, 0,0,
                                       MLEN*BSZ, DMODEL, 0, mAh, mAl, 12, 0);
        gemm_tc<<<dim3(6,1,1),256,GT_SMEM_N2>>>(cAh, cAl, 0,0,
            qkvTh+wq+(long)6*12*TUSH, qkvTl+wq+(long)6*12*TUSH, 0,0,
            heads + ND, TND, 0,0, 0,0,0, CLEN*BSZ, 2*ND, DMODEL, 0,0,0,1,1);
        gemm_tc<<<dim3(6,16,1),256,GT_SMEM_N2>>>(mAh, mAl, 0,0,
            qkvTh+wq+(long)6*12*TUSH, qkvTl+wq+(long)6*12*TUSH, 0,0,
            heads + (size_t)CLEN*BSZ*TND + ND, TND, 0,0, 0,0,0, MLEN*BSZ, 2*ND, DMODEL, 0,0,0,1,1);
        gemm_tc<<<dim3(3,9,1),256,GT_SMEM_N2>>>(rAh, rAl, 0,0,
            rnTh+(long)l*6*12*TUSH, rnTl+(long)l*6*12*TUSH, 0,0,
            rk, ND, 0,0, 0,0,0, KLEN, ND, DMODEL, 0,0,0,1,1);

        pack_nT<<<dim3(4,1,NBATCH),256>>>(q, BSZ*TND, NH, TND, DH, QLEN, DH, r_w_bias,
                                          qA0h, qA0l, 1, (long)4*TUSH);
        pack_nT<<<dim3(4,1,NBATCH),256>>>(q, BSZ*TND, NH, TND, DH, QLEN, DH, r_r_bias,
                                          qA1h, qA1l, 1, (long)4*TUSH);
        pack_nT<<<dim3(9,1,NBATCH),256>>>(heads + ND, BSZ*TND, NH, TND, DH, KLEN, DH, 0,
                                          ktTh, ktTl, 1, (long)9*TUSH);
        pack_nT<<<dim3(9,1,12),256>>>(rk, ND, NH, 0, DH, KLEN, DH, 0,
                                      rkTh, rkTl, 1, (long)9*TUSH);
        pack_wT<<<dim3(1,17,NBATCH),256>>>(heads + 2*ND, BSZ*TND, NH, TND, DH, KLEN, DH,
                                           vTh, vTl, 17, (long)17*TUSH);

        gemm_tc<<<dim3(9,4,NBATCH),256,GT_SMEM_SB>>>(qA0h, qA0l, (long)NH*4*TUSH, (long)4*TUSH,
            ktTh, ktTl, (long)NH*9*TUSH, (long)9*TUSH,
            ac, KLEN, (long)NH*QLEN*KLEN, (long)QLEN*KLEN, 0,0,0, QLEN, KLEN, DH, 0,0,2,0,0);
        gemm_tc<<<dim3(9,4,NBATCH),256,GT_SMEM_SB>>>(qA1h, qA1l, (long)NH*4*TUSH, (long)4*TUSH,
            rkTh, rkTl, 0, (long)9*TUSH,
            bd, KLEN, (long)NH*QLEN*KLEN, (long)QLEN*KLEN, 0,0,0, QLEN, KLEN, DH, 0,0,1,0,0);

        softmax_kernel<<<dim3(QLEN,NBATCH),256>>>();

        gemm_tc<<<dim3(1,4,NBATCH),256,GT_SMEM_PV>>>(prTh, 0, (long)NH*4*17*TUSH, (long)4*17*TUSH,
            vTh, vTl, (long)NH*17*TUSH, (long)17*TUSH,
            av, BSZ*DMODEL, DMODEL, DH, 0,0,0, QLEN, DH, KLEN, 0,0,0,1,0);

        pack_nT<<<dim3(16,12,1),256>>>(av, DMODEL, 1, 0,0, QB, DMODEL, 0, avAh, avAl, 12, 0);
        gemm_tc<<<dim3(3,16,1),256,GT_SMEM_N2>>>(avAh, avAl, 0,0,
            oTh+(long)l*6*12*TUSH, oTl+(long)l*6*12*TUSH, 0,0,
            ff, DMODEL, 0,0, 0,0,0, QB, DMODEL, ND, 0,0,0,1,1);
        add_ln_kernel<<<QB,256>>>(h, ff, ln1_g + l*DMODEL, ln1_b + l*DMODEL, hAh, hAl);

        gemm_tc<<<dim3(12,16,1),256,GT_SMEM_N2>>>(hAh, hAl, 0,0,
            w1Th+(long)l*24*12*TUSH, w1Tl+(long)l*24*12*TUSH, 0,0,
            0, 0, 0,0, ffAh, ffAl, 48, QB, DFF, DMODEL, b1 + (size_t)l*DFF, 1,0,1,1);
        gemm_tc<<<dim3(3,16,1),256,GT_SMEM_N2>>>(ffAh, ffAl, 0,0,
            w2Th+(long)l*6*48*TUSH, w2Tl+(long)l*6*48*TUSH, 0,0,
            av, DMODEL, 0,0, 0,0,0, QB, DMODEL, DFF, b2 + (size_t)l*DMODEL, 0,0,1,1);
        add_ln_kernel<<<QB,256>>>(h, av, ln2_g + l*DMODEL, ln2_b + l*DMODEL, hAh, hAl);
    }

    // vocab proj: 39 nt2 blocks cover cols 0..9983 (B tiles 0..77), nt1 remainder tile 78
    gemm_tc<<<dim3(39,16,1),256,GT_SMEM_N2>>>(hAh, hAl, 0,0, pTh, pTl, 0,0,
        out, NV, 0,0, 0,0,0, QB, NV, DMODEL, proj_b, 0,0,1,1);
    gemm_tc<<<dim3(1,16,1),256,GT_SMEM_N1>>>(hAh, hAl, 0,0,
        pTh + (long)78*12*TUSH, pTl + (long)78*12*TUSH, 0,0,
        out + 9984, NV, 0,0, 0,0,0, QB, NV - 9984, DMODEL, proj_b + 9984, 0,0,1,0);
}

// round 16
// speedup vs baseline: 1.0806x; 1.0806x over previous
#include <cuda_runtime.h>
#include <math.h>
#include <stdint.h>

#define NLAYER 12
#define NH 12
#define DH 64
#define DMODEL 768
#define DFF 3072
#define NV 10000
#define QLEN 512
#define MLEN 512
#define CLEN 32
#define BSZ 4
#define KLEN 1056
#define QB (QLEN*BSZ)
#define KB (KLEN*BSZ)
#define TND (3*NH*DH)
#define ND (NH*DH)
#define NBATCH (BSZ*NH)
#define TUSH 8192

#if defined(__CUDA_ARCH_FEAT_SM103_ALL) || defined(__CUDA_ARCH_FEAT_SM100_ALL)
#define HAS_TC 1
#else
#define HAS_TC 0
#endif

// ---------------- fp32 scratch ----------------
__device__ float g_h[QB*DMODEL];
__device__ float g_r[KLEN*DMODEL];
__device__ float g_heads[(size_t)KB*TND];
__device__ float g_rk[KLEN*DMODEL];
__device__ float g_ac[(size_t)NBATCH*QLEN*KLEN];
__device__ float g_bd[(size_t)NBATCH*QLEN*KLEN];
__device__ float g_av[QB*DMODEL];
__device__ float g_ff[(size_t)QB*DMODEL];
// ---------------- tiled bf16 hi/lo scratch ----------------
#define DECL(name, n) __device__ __align__(16) unsigned short name##_h[(size_t)(n)], name##_l[(size_t)(n)]
DECL(g_qkvT, (size_t)NLAYER*18*12*TUSH);
DECL(g_rnT,  (size_t)NLAYER*6*12*TUSH);
DECL(g_oT,   (size_t)NLAYER*6*12*TUSH);
DECL(g_w1T,  (size_t)NLAYER*24*12*TUSH);
DECL(g_w2T,  (size_t)NLAYER*6*48*TUSH);
DECL(g_pT,   (size_t)80*12*TUSH);
DECL(g_ktT,  (size_t)NBATCH*9*TUSH);
DECL(g_rkT,  (size_t)12*9*TUSH);
DECL(g_vT,   (size_t)NBATCH*17*TUSH);
DECL(g_prT,  (size_t)NBATCH*4*17*TUSH);
DECL(g_qA0,  (size_t)NBATCH*4*TUSH);
DECL(g_qA1,  (size_t)NBATCH*4*TUSH);
DECL(g_hA,   (size_t)16*12*TUSH);
DECL(g_mA,   (size_t)16*12*TUSH);
DECL(g_cA,   (size_t)12*TUSH);
DECL(g_rA,   (size_t)9*12*TUSH);
DECL(g_avA,  (size_t)16*12*TUSH);
DECL(g_ffA,  (size_t)16*48*TUSH);
#undef DECL

// ---------------- PTX helpers ----------------
__device__ __forceinline__ uint32_t smem_u32(const void* p) {
    uint32_t a;
    asm("{ .reg .u64 t; cvta.to.shared.u64 t, %1; cvt.u32.u64 %0, t; }" : "=r"(a) : "l"(p));
    return a;
}
#define MBAR_INIT(a,c) asm volatile("mbarrier.init.shared.b64 [%0], %1;" :: "r"((uint32_t)(a)), "r"((uint32_t)(c)) : "memory")
#define MBAR_INVAL(a)  asm volatile("mbarrier.inval.shared.b64 [%0];" :: "r"((uint32_t)(a)) : "memory")
#define MBAR_EXPECT(a,b) asm volatile("mbarrier.arrive.expect_tx.shared.b64 _, [%0], %1;" :: "r"((uint32_t)(a)), "r"((uint32_t)(b)) : "memory")
#define MBAR_WAIT(a,p) do { uint32_t _m=(uint32_t)(a), _p=(uint32_t)(p); \
    asm volatile("{\n\t.reg .pred P1;\n\tWL_%=:\n\t" \
        "mbarrier.try_wait.parity.acquire.cta.shared::cta.b64 P1, [%0], %1, 0x989680;\n\t" \
        "@P1 bra.uni WD_%=;\n\tbra.uni WL_%=;\n\tWD_%=:\n\t}" :: "r"(_m), "r"(_p) : "memory"); } while(0)
#define BULK(dst, src, bytes, mbar) \
    asm volatile("cp.async.bulk.shared::cluster.global.mbarrier::complete_tx::bytes [%0], [%1], %2, [%3];" \
        :: "r"((uint32_t)(dst)), "l"(src), "r"((uint32_t)(bytes)), "r"((uint32_t)(mbar)) : "memory")
#define TC_ALLOC(a,n)   asm volatile("tcgen05.alloc.cta_group::1.sync.aligned.shared::cta.b32 [%0], %1;" :: "r"((uint32_t)(a)), "r"((uint32_t)(n)) : "memory")
#define TC_DEALLOC(t,n) asm volatile("tcgen05.dealloc.cta_group::1.sync.aligned.b32 %0, %1;" :: "r"(t), "r"((uint32_t)(n)))
#define TC_RELINQ()     asm volatile("tcgen05.relinquish_alloc_permit.cta_group::1.sync.aligned;")
#define TC_COMMIT(a)    asm volatile("tcgen05.commit.cta_group::1.mbarrier::arrive::one.shared::cluster.b64 [%0];" :: "r"((uint32_t)(a)) : "memory")
#define TC_WAIT_LD()    asm volatile("tcgen05.wait::ld.sync.aligned;" ::: "memory")
#define TC_FENCE_AFT()  asm volatile("tcgen05.fence::after_thread_sync;" ::: "memory")
#define TC_LD_X32(r, ta) asm volatile( \
    "tcgen05.ld.sync.aligned.32x32b.x32.b32 " \
    "{%0,%1,%2,%3,%4,%5,%6,%7,%8,%9,%10,%11,%12,%13,%14,%15," \
    "%16,%17,%18,%19,%20,%21,%22,%23,%24,%25,%26,%27,%28,%29,%30,%31}, [%32];" \
    : "=r"((r)[0]),"=r"((r)[1]),"=r"((r)[2]),"=r"((r)[3]),"=r"((r)[4]),"=r"((r)[5]),"=r"((r)[6]),"=r"((r)[7]), \
      "=r"((r)[8]),"=r"((r)[9]),"=r"((r)[10]),"=r"((r)[11]),"=r"((r)[12]),"=r"((r)[13]),"=r"((r)[14]),"=r"((r)[15]), \
      "=r"((r)[16]),"=r"((r)[17]),"=r"((r)[18]),"=r"((r)[19]),"=r"((r)[20]),"=r"((r)[21]),"=r"((r)[22]),"=r"((r)[23]), \
      "=r"((r)[24]),"=r"((r)[25]),"=r"((r)[26]),"=r"((r)[27]),"=r"((r)[28]),"=r"((r)[29]),"=r"((r)[30]),"=r"((r)[31]) \
    : "r"(ta))

static constexpr uint64_t DESC_BASE =
    (uint64_t(2) << 61) | (uint64_t(1) << 46) | (uint64_t(64) << 32) | (uint64_t(1) << 16);
#define MK_DESC(a) (DESC_BASE | ((uint64_t)((a) >> 4) & 0x3FFF))
#define IDESC_N128 0x8200490u
#define IDESC_N64  0x8100490u

#if HAS_TC
__device__ __forceinline__ void mma_bf16(uint32_t d, uint64_t ad, uint64_t bd,
                                         uint32_t idesc, uint32_t en) {
    asm volatile(
        "{\n\t.reg .pred p;\n\tsetp.ne.u32 p, %4, 0;\n\t"
        "tcgen05.mma.cta_group::1.kind::f16 [%0], %1, %2, %3, {%5, %5, %5, %5}, p;\n\t}"
        :: "r"(d), "l"(ad), "l"(bd), "r"(idesc), "r"(en), "r"(0u) : "memory");
}
#endif

__device__ __forceinline__ void split1(float x, unsigned short& h, unsigned short& l) {
    unsigned u = __float_as_uint(x);
    unsigned r = (u + 0x7fffu + ((u >> 16) & 1u)) & 0xffff0000u;
    h = (unsigned short)(r >> 16);
    unsigned v = __float_as_uint(x - __uint_as_float(r));
    l = (unsigned short)((v + 0x7fffu + ((v >> 16) & 1u)) >> 16);
}
__device__ __forceinline__ float tread_f(const unsigned short* Hh, const unsigned short* Hl,
                                         long zoff, int kts, int r, int c) {
    long tile = (long)(r >> 7) * kts + (c >> 6);
    uint32_t bo = ((uint32_t)(r & 127) << 7) | ((uint32_t)(c & 63) << 1);
    bo ^= (bo >> 3) & 0x70;
    long o = zoff + tile * TUSH + (bo >> 1);
    float hv = __uint_as_float((unsigned)Hh[o] << 16);
    return Hl ? hv + __uint_as_float((unsigned)Hl[o] << 16) : hv;
}
__device__ __forceinline__ void twrite(unsigned short* Dh, unsigned short* Dl,
                                       int kts, int r, int c, float v) {
    long tile = (long)(r >> 7) * kts + (c >> 6);
    uint32_t bo = ((uint32_t)(r & 127) << 7) | ((uint32_t)(c & 63) << 1);
    bo ^= (bo >> 3) & 0x70;
    long o = tile * TUSH + (bo >> 1);
    unsigned short h, l;
    split1(v, h, l);
    Dh[o] = h; Dl[o] = l;
}

__device__ __forceinline__ float warp_sum(float v) {
    #pragma unroll
    for (int o = 16; o; o >>= 1) v += __shfl_xor_sync(0xffffffffu, v, o);
    return v;
}
__device__ __forceinline__ float warp_max(float v) {
    #pragma unroll
    for (int o = 16; o; o >>= 1) v = fmaxf(v, __shfl_xor_sync(0xffffffffu, v, o));
    return v;
}
__device__ __forceinline__ float block_sum(float v, float* red) {
    v = warp_sum(v);
    __syncthreads();
    if ((threadIdx.x & 31) == 0) red[threadIdx.x >> 5] = v;
    __syncthreads();
    float r = 0.f;
    #pragma unroll
    for (int k = 0; k < 8; k++) r += red[k];
    return r;
}

// ---------------- elementwise ----------------
__global__ void embed_kernel(const int* __restrict__ x, const float* __restrict__ emb) {
    int idx = blockIdx.x * 256 + threadIdx.x;
    if (idx >= QB * DMODEL) return;
    int row = idx / DMODEL, d = idx % DMODEL;
    float v = emb[(size_t)x[row] * DMODEL + d] * sqrtf(768.0f);
    g_h[idx] = v;
    twrite(g_hA_h, g_hA_l, 12, row, d, v);
}
__global__ void posemb_kernel() {
    int idx = blockIdx.x * 256 + threadIdx.x;
    if (idx >= KLEN * DMODEL) return;
    int p = idx / DMODEL, d = idx % DMODEL;
    float pos = (float)(KLEN - 1 - p);
    int dd = (d < 384) ? d : d - 384;
    float s = pos / powf(10000.0f, (float)(2 * dd) / 768.0f);
    g_r[idx] = (d < 384) ? sinf(s) : cosf(s);
}

// ---- pack (no transpose) ----
__global__ void __launch_bounds__(256)
pack_nT(const float* __restrict__ src, int lds, int zq, long offB, long offN,
        int rowsN, int colsK, const float* __restrict__ bias,
        unsigned short* __restrict__ dh, unsigned short* __restrict__ dl,
        int kts, long zStr)
{
    int z = blockIdx.z, bb = z / zq, nn = z % zq;
    const float* s = src + (long)bb * offB + (long)nn * offN;
    const float* bi = bias ? (bias + (long)nn * DH) : (const float*)0;
    long dbase = (long)z * zStr + ((long)blockIdx.x * kts + blockIdx.y) * TUSH;
    int n0 = blockIdx.x << 7, k0 = blockIdx.y << 6;
    #pragma unroll
    for (int g = 0; g < 4; g++) {
        int gi = threadIdx.x + g * 256;
        int n = gi >> 3, kg = gi & 7;
        int r = n0 + n, c = k0 + kg * 8;
        float xv[8] = {0,0,0,0,0,0,0,0};
        if (r < rowsN && c < colsK) {
            const float* p = s + (long)r * lds + c;
            float4 v0 = *(const float4*)p, v1 = *(const float4*)(p + 4);
            xv[0]=v0.x; xv[1]=v0.y; xv[2]=v0.z; xv[3]=v0.w;
            xv[4]=v1.x; xv[5]=v1.y; xv[6]=v1.z; xv[7]=v1.w;
            if (bi) {
                #pragma unroll
                for (int j = 0; j < 8; j++) xv[j] += bi[c + j];
            }
        }
        unsigned short h[8], l[8];
        #pragma unroll
        for (int j = 0; j < 8; j++) split1(xv[j], h[j], l[j]);
        uint32_t bo = ((uint32_t)n << 7) | ((uint32_t)kg << 4);
        uint32_t sw = bo ^ ((bo >> 3) & 0x70);
        *(uint4*)(dh + dbase + (sw >> 1)) = make_uint4(((unsigned)h[1]<<16)|h[0], ((unsigned)h[3]<<16)|h[2],
                                                       ((unsigned)h[5]<<16)|h[4], ((unsigned)h[7]<<16)|h[6]);
        *(uint4*)(dl + dbase + (sw >> 1)) = make_uint4(((unsigned)l[1]<<16)|l[0], ((unsigned)l[3]<<16)|l[2],
                                                       ((unsigned)l[5]<<16)|l[4], ((unsigned)l[7]<<16)|l[6]);
    }
}

// ---- pack with transpose ----
__global__ void __launch_bounds__(256)
pack_wT(const float* __restrict__ src, int lds, int zq, long offB, long offN,
        int srcRows, int srcCols,
        unsigned short* __restrict__ dh, unsigned short* __restrict__ dl,
        int kts, long zStr)
{
    __shared__ float t[64][129];
    int z = blockIdx.z, bb = z / zq, nn = z % zq;
    const float* s = src + (long)bb * offB + (long)nn * offN;
    long dbase = (long)z * zStr + ((long)blockIdx.x * kts + blockIdx.y) * TUSH;
    int n0 = blockIdx.x << 7, k0 = blockIdx.y << 6;
    #pragma unroll
    for (int i = 0; i < 32; i++) {
        int idx = threadIdx.x + i * 256;
        int kr = idx >> 7, nc = idx & 127;
        float v = 0.f;
        if (k0 + kr < srcRows && n0 + nc < srcCols)
            v = s[(long)(k0 + kr) * lds + n0 + nc];
        t[kr][nc] = v;
    }
    __syncthreads();
    #pragma unroll
    for (int g = 0; g < 4; g++) {
        int gi = threadIdx.x + g * 256;
        int n = gi >> 3, kg = gi & 7;
        unsigned short h[8], l[8];
        #pragma unroll
        for (int j = 0; j < 8; j++) split1(t[kg * 8 + j][n], h[j], l[j]);
        uint32_t bo = ((uint32_t)n << 7) | ((uint32_t)kg << 4);
        uint32_t sw = bo ^ ((bo >> 3) & 0x70);
        *(uint4*)(dh + dbase + (sw >> 1)) = make_uint4(((unsigned)h[1]<<16)|h[0], ((unsigned)h[3]<<16)|h[2],
                                                       ((unsigned)h[5]<<16)|h[4], ((unsigned)h[7]<<16)|h[6]);
        *(uint4*)(dl + dbase + (sw >> 1)) = make_uint4(((unsigned)l[1]<<16)|l[0], ((unsigned)l[3]<<16)|l[2],
                                                       ((unsigned)l[5]<<16)|l[4], ((unsigned)l[7]<<16)|l[6]);
    }
}

// ---------------- GEMM ----------------
#define GT_SMEM_SB (1024 + 128 * 132 * 4)
#define GT_SMEM_N1 (1024 + 2 * 65536)
#define GT_SMEM_N2 (1024 + 2 * 98304)
#define GT_SMEM_PV (1024 + 2 * 49152)

__global__ void __launch_bounds__(256)
gemm_tc(const unsigned short* __restrict__ Ahi, const unsigned short* __restrict__ Alo,
        long aZb, long aZn,
        const unsigned short* __restrict__ Bhi, const unsigned short* __restrict__ Blo,
        long bZb, long bZn,
        float* __restrict__ C, int ldc, long cZb, long cZn,
        unsigned short* __restrict__ Coh, unsigned short* __restrict__ Col, int coKts,
        int M, int N, int K,
        const float* __restrict__ cbias, int relu, int mode, int dbuf, int nt2)
{
    extern __shared__ char smem[];
    const int tid = threadIdx.x;
    const int bb = blockIdx.z / NH, nn = blockIdx.z % NH;
    const int row0 = blockIdx.y * 128;
    const int col0 = blockIdx.x * (nt2 ? 256 : 128);
    if (mode == 2 && col0 > row0 + (CLEN + MLEN + 127)) return;
    if (mode == 1 && col0 + 127 < (QLEN - 1) - (row0 + 127)) return;
    const long aoff = (long)bb * aZb + (long)nn * aZn;
    const long boff = (long)bb * bZb + (long)nn * bZn;
    float* Cz = C ? (C + (long)bb * cZb + (long)nn * cZn) : (float*)0;
    const int KT = (K + 63) >> 6;
    const int hasAl = (Alo != 0);

#if HAS_TC
    const uint32_t sb = smem_u32(smem);
    const int wid = tid >> 5, lane = tid & 31;
    const uint32_t idesc = (N <= 64) ? IDESC_N64 : IDESC_N128;
    const uint32_t aB = hasAl ? 32768u : 16384u;
    const uint32_t bufB = aB + (nt2 ? 65536u : 32768u);
    if (wid == 0) { TC_ALLOC(sb, nt2 ? 256 : 128); TC_RELINQ(); }
    if (tid == 0) {
        MBAR_INIT(sb + 16, 1); MBAR_INIT(sb + 24, 1);
        MBAR_INIT(sb + 32, 1); MBAR_INIT(sb + 40, 1);
    }
    __syncthreads();
    uint32_t tmem;
    asm volatile("ld.shared.b32 %0, [%1];" : "=r"(tmem) : "r"(sb));

    if (tid == 0) {
        const long aT0 = aoff + (long)(row0 >> 7) * KT * TUSH;
        const int bt = nt2 ? blockIdx.x * 2 : blockIdx.x;
        const long bT0 = boff + (long)bt * KT * TUSH;
        const long bT1 = boff + (long)(bt + 1) * KT * TUSH;
        int pf[2] = {0, 0}, pd[2] = {0, 0};
#define ISSUE(t, b) do { \
            uint32_t _fb = sb + 16 + (uint32_t)(b) * 16; \
            uint32_t _bs = sb + 1024 + (uint32_t)(b) * bufB; \
            MBAR_EXPECT(_fb, bufB); \
            BULK(_bs, Ahi + aT0 + (long)(t) * TUSH, 16384, _fb); \
            if (hasAl) BULK(_bs + 16384, Alo + aT0 + (long)(t) * TUSH, 16384, _fb); \
            BULK(_bs + aB,         Bhi + bT0 + (long)(t) * TUSH, 16384, _fb); \
            BULK(_bs + aB + 16384, Blo + bT0 + (long)(t) * TUSH, 16384, _fb); \
            if (nt2) { \
                BULK(_bs + aB + 32768, Bhi + bT1 + (long)(t) * TUSH, 16384, _fb); \
                BULK(_bs + aB + 49152, Blo + bT1 + (long)(t) * TUSH, 16384, _fb); \
            } \
        } while (0)
        ISSUE(0, 0);
        for (int t = 0; t < KT; t++) {
            const int buf = dbuf ? (t & 1) : 0;
            if (dbuf && t + 1 < KT) {
                int nb = (t + 1) & 1;
                if (t + 1 >= 2) { MBAR_WAIT(sb + 24 + (uint32_t)nb * 16, pd[nb] & 1); pd[nb]++; }
                ISSUE(t + 1, nb);
            }
            MBAR_WAIT(sb + 16 + (uint32_t)buf * 16, pf[buf] & 1); pf[buf]++;
            const uint32_t bs = sb + 1024 + (uint32_t)buf * bufB;
            uint64_t dAh = MK_DESC(bs);
            uint64_t dAl = MK_DESC(bs + 16384);
            uint64_t dB0h = MK_DESC(bs + aB);
            uint64_t dB0l = MK_DESC(bs + aB + 16384);
            uint64_t dB1h = MK_DESC(bs + aB + 32768);
            uint64_t dB1l = MK_DESC(bs + aB + 49152);
            #pragma unroll
            for (int ks = 0; ks < 4; ks++) {
                uint32_t en0 = (t > 0 || ks > 0) ? 1u : 0u;
                mma_bf16(tmem, dAh + ks*2, dB0h + ks*2, idesc, en0);
                mma_bf16(tmem, dAh + ks*2, dB0l + ks*2, idesc, 1u);
                if (hasAl) mma_bf16(tmem, dAl + ks*2, dB0h + ks*2, idesc, 1u);
                if (nt2) {
                    mma_bf16(tmem + 128, dAh + ks*2, dB1h + ks*2, idesc, en0);
                    mma_bf16(tmem + 128, dAh + ks*2, dB1l + ks*2, idesc, 1u);
                    if (hasAl) mma_bf16(tmem + 128, dAl + ks*2, dB1h + ks*2, idesc, 1u);
                }
            }
            TC_COMMIT(sb + 24 + (uint32_t)buf * 16);
            if (!dbuf && t + 1 < KT) {
                MBAR_WAIT(sb + 24, pd[0] & 1); pd[0]++;
                ISSUE(t + 1, 0);
            }
        }
        if (dbuf) {
            if (KT >= 2) {
                int b2 = (KT - 2) & 1;
                MBAR_WAIT(sb + 24 + (uint32_t)b2 * 16, pd[b2] & 1); pd[b2]++;
            }
            int b1 = (KT - 1) & 1;
            MBAR_WAIT(sb + 24 + (uint32_t)b1 * 16, pd[b1] & 1);
        } else {
            MBAR_WAIT(sb + 24, pd[0] & 1);
        }
#undef ISSUE
    }
    __syncthreads();
    TC_FENCE_AFT();

    for (int ct = 0; ct <= nt2; ct++) {
        float* Cs = (float*)(smem + 1024);
        int col0e = col0 + ct * 128;
        int sub = wid & 3, ch = wid >> 2;
        int rl = sub * 32 + lane;
        #pragma unroll
        for (int half = 0; half < 2; half++) {
            uint32_t dr[32];
            TC_LD_X32(dr, tmem + (uint32_t)(ct * 128 + ch * 64 + half * 32));
            TC_WAIT_LD();
            #pragma unroll
            for (int c = 0; c < 32; c++)
                Cs[rl * 132 + ch * 64 + half * 32 + c] = __uint_as_float(dr[c]);
        }
        __syncthreads();
        if (Coh) {
            long tb = ((long)(row0 >> 7) * coKts + (col0e >> 6)) * TUSH;
            #pragma unroll
            for (int half = 0; half < 2; half++) {
                long dbase = tb + (long)half * TUSH;
                #pragma unroll
                for (int g = 0; g < 4; g++) {
                    int gi = tid + g * 256;
                    int n = gi >> 3, kg = gi & 7;
                    unsigned short h8[8], l8[8];
                    #pragma unroll
                    for (int j = 0; j < 8; j++) {
                        int c = half * 64 + kg * 8 + j;
                        int cg = col0e + c;
                        float v = 0.f;
                        if (row0 + n < M && cg < N) {
                            v = Cs[n * 132 + c];
                            if (cbias) v += cbias[cg];
                            if (relu) v = fmaxf(v, 0.f);
                        }
                        split1(v, h8[j], l8[j]);
                    }
                    uint32_t bo = ((uint32_t)n << 7) | ((uint32_t)kg << 4);
                    uint32_t sw = bo ^ ((bo >> 3) & 0x70);
                    *(uint4*)(Coh + dbase + (sw >> 1)) = make_uint4(((unsigned)h8[1]<<16)|h8[0], ((unsigned)h8[3]<<16)|h8[2],
                                                                    ((unsigned)h8[5]<<16)|h8[4], ((unsigned)h8[7]<<16)|h8[6]);
                    *(uint4*)(Col + dbase + (sw >> 1)) = make_uint4(((unsigned)l8[1]<<16)|l8[0], ((unsigned)l8[3]<<16)|l8[2],
                                                                    ((unsigned)l8[5]<<16)|l8[4], ((unsigned)l8[7]<<16)|l8[6]);
                }
            }
        } else {
            for (int i2 = tid; i2 < 128 * 32; i2 += 256) {
                int row = i2 >> 5, c4 = (i2 & 31) << 2;
                int r = row0 + row;
                if (r >= M) continue;
                int cg = col0e + c4;
                if (cg >= N) continue;
                float4 v = *(float4*)&Cs[row * 132 + c4];
                float vv[4] = {v.x, v.y, v.z, v.w};
                if (cg + 3 < N) {
                    if (cbias) {
                        vv[0] += cbias[cg]; vv[1] += cbias[cg+1];
                        vv[2] += cbias[cg+2]; vv[3] += cbias[cg+3];
                    }
                    if (relu) {
                        #pragma unroll
                        for (int j = 0; j < 4; j++) vv[j] = fmaxf(vv[j], 0.f);
                    }
                    *(float4*)&Cz[(long)r * ldc + cg] = make_float4(vv[0], vv[1], vv[2], vv[3]);
                } else {
                    #pragma unroll
                    for (int j = 0; j < 4; j++) {
                        int c = cg + j;
                        if (c < N) {
                            float w = vv[j];
                            if (cbias) w += cbias[c];
                            if (relu) w = fmaxf(w, 0.f);
                            Cz[(long)r * ldc + c] = w;
                        }
                    }
                }
            }
        }
        __syncthreads();
    }
    if (tid == 0) { MBAR_INVAL(sb + 16); MBAR_INVAL(sb + 24); MBAR_INVAL(sb + 32); MBAR_INVAL(sb + 40); }
    if (wid == 0) TC_DEALLOC(tmem, nt2 ? 256 : 128);
#else
    // ---------- SIMT fallback ----------
    float* As = (float*)smem;
    float* Bs = (float*)smem + 16 * 132;
    const int ty4 = (tid >> 4) << 2, tx4 = (tid & 15) << 2;
    for (int ct = 0; ct <= nt2; ct++) {
        int col0e = col0 + ct * 128;
        float acc[8][8] = {};
        for (int k0 = 0; k0 < K; k0 += 16) {
            #pragma unroll
            for (int s = 0; s < 2; s++) {
                int idx = tid + s * 256;
                int m = idx >> 2, kc = (idx & 3) << 2;
                #pragma unroll
                for (int j = 0; j < 4; j++) {
                    float v = 0.f;
                    if (row0 + m < M && k0 + kc + j < K)
                        v = tread_f(Ahi, Alo, aoff, KT, row0 + m, k0 + kc + j);
                    As[(kc + j) * 132 + m] = v;
                }
            }
            #pragma unroll
            for (int s = 0; s < 8; s++) {
                int idx = tid + s * 256;
                int n = idx >> 4, kk2 = idx & 15;
                float v = 0.f;
                if (col0e + n < N && k0 + kk2 < K)
                    v = tread_f(Bhi, Blo, boff, KT, col0e + n, k0 + kk2);
                Bs[kk2 * 128 + n] = v;
            }
            __syncthreads();
            #pragma unroll
            for (int k = 0; k < 16; k++) {
                float4 xa0 = *(const float4*)&As[k*132 + ty4];
                float4 xa1 = *(const float4*)&As[k*132 + ty4 + 64];
                float4 xb0 = *(const float4*)&Bs[k*128 + tx4];
                float4 xb1 = *(const float4*)&Bs[k*128 + tx4 + 64];
                float av8[8] = {xa0.x,xa0.y,xa0.z,xa0.w, xa1.x,xa1.y,xa1.z,xa1.w};
                float bv8[8] = {xb0.x,xb0.y,xb0.z,xb0.w, xb1.x,xb1.y,xb1.z,xb1.w};
                #pragma unroll
                for (int i = 0; i < 8; i++)
                    #pragma unroll
                    for (int j = 0; j < 8; j++) acc[i][j] += av8[i] * bv8[j];
            }
            __syncthreads();
        }
        #pragma unroll
        for (int i = 0; i < 8; i++) {
            int r = row0 + ty4 + ((i < 4) ? i : 60 + i);
            if (r >= M) continue;
            #pragma unroll
            for (int j = 0; j < 8; j++) {
                int cg = col0e + tx4 + ((j < 4) ? j : 60 + j);
                if (cg >= N) continue;
                float v = acc[i][j];
                if (cbias) v += cbias[cg];
                if (relu) v = fmaxf(v, 0.f);
                if (Coh) twrite(Coh, Col, coKts, r, cg, v);
                else Cz[(long)r * ldc + cg] = v;
            }
        }
        __syncthreads();
    }
#endif
}

// ---------------- softmax: rel-shift folded; probs out tiled bf16 (hi only) ----------------
__global__ void __launch_bounds__(256) softmax_kernel() {
    int i = blockIdx.x, z = blockIdx.y;
    size_t rbase = ((size_t)z * QLEN + i) * KLEN;
    const float* row = g_ac + rbase;
    const float* bdrow = g_bd + rbase;
    int jmax = i + CLEN + MLEN;
    __shared__ float s[KLEN];
    __shared__ float red[8];
    int tid = threadIdx.x;
    float lmax = -3.0e38f;
    for (int j = tid; j <= jmax; j += 256) {
        float v = (row[j] + bdrow[j + QLEN - 1 - i]) * 0.125f;
        s[j] = v;
        lmax = fmaxf(lmax, v);
    }
    lmax = warp_max(lmax);
    __syncthreads();
    if ((tid & 31) == 0) red[tid >> 5] = lmax;
    __syncthreads();
    float m = red[0];
    #pragma unroll
    for (int k = 1; k < 8; k++) m = fmaxf(m, red[k]);
    float lsum = 0.f;
    for (int j = tid; j <= jmax; j += 256) { float e = expf(s[j] - m); s[j] = e; lsum += e; }
    float inv = 1.0f / block_sum(lsum, red);
    __syncthreads();
    long zb = (long)z * (4 * 17 * TUSH) + ((long)(i >> 7) * 17) * TUSH;
    for (int j = tid; j < 17 * 64; j += 256) {
        float p = (j <= jmax && j < KLEN) ? s[j] * inv : 0.0f;
        unsigned u = __float_as_uint(p);
        unsigned short h = (unsigned short)((u + 0x7fffu + ((u >> 16) & 1u)) >> 16);
        uint32_t bo = ((uint32_t)(i & 127) << 7) | ((uint32_t)(j & 63) << 1);
        bo ^= (bo >> 3) & 0x70;
        g_prT_h[zb + (long)(j >> 6) * TUSH + (bo >> 1)] = h;
    }
}

// ---------------- h = LN(h+res); emits tiled bf16 hA ----------------
__global__ void __launch_bounds__(256)
add_ln_kernel(float* __restrict__ h, const float* __restrict__ res,
              const float* __restrict__ g, const float* __restrict__ b,
              unsigned short* __restrict__ dh, unsigned short* __restrict__ dl)
{
    __shared__ float red[8];
    int row = blockIdx.x, tid = threadIdx.x;
    size_t base = (size_t)row * DMODEL;
    float x0 = h[base + tid]       + res[base + tid];
    float x1 = h[base + tid + 256] + res[base + tid + 256];
    float x2 = h[base + tid + 512] + res[base + tid + 512];
    float mean = block_sum(x0 + x1 + x2, red) * (1.0f / 768.0f);
    float d0 = x0 - mean, d1 = x1 - mean, d2 = x2 - mean;
    float inv = rsqrtf(block_sum(d0*d0 + d1*d1 + d2*d2, red) * (1.0f / 768.0f) + 1e-5f);
    float y0 = d0 * inv * g[tid]       + b[tid];
    float y1 = d1 * inv * g[tid + 256] + b[tid + 256];
    float y2 = d2 * inv * g[tid + 512] + b[tid + 512];
    h[base + tid]       = y0;
    h[base + tid + 256] = y1;
    h[base + tid + 512] = y2;
    twrite(dh, dl, 12, row, tid,       y0);
    twrite(dh, dl, 12, row, tid + 256, y1);
    twrite(dh, dl, 12, row, tid + 512, y2);
}

// ---------------- host ----------------
extern "C" void kernel_launch(void* const* d_in, const int* in_sizes, int n_in,
                              void* d_out, int out_size)
{
    const int*   x         = (const int*)  d_in[0];
    const float* condition = (const float*)d_in[1];
    const float* mems      = (const float*)d_in[2];
    const float* emb       = (const float*)d_in[3];
    const float* qkv_w     = (const float*)d_in[4];
    const float* r_net_w   = (const float*)d_in[5];
    const float* o_w       = (const float*)d_in[6];
    const float* ln1_g     = (const float*)d_in[7];
    const float* ln1_b     = (const float*)d_in[8];
    const float* w1        = (const float*)d_in[9];
    const float* b1        = (const float*)d_in[10];
    const float* w2        = (const float*)d_in[11];
    const float* b2        = (const float*)d_in[12];
    const float* ln2_g     = (const float*)d_in[13];
    const float* ln2_b     = (const float*)d_in[14];
    const float* r_w_bias  = (const float*)d_in[15];
    const float* r_r_bias  = (const float*)d_in[16];
    const float* proj_w    = (const float*)d_in[17];
    const float* proj_b    = (const float*)d_in[18];
    float* out = (float*)d_out;

    cudaFuncSetAttribute(gemm_tc, cudaFuncAttributeMaxDynamicSharedMemorySize, GT_SMEM_N2);

    float *h, *r, *heads, *rk, *ac, *bd, *av, *ff;
    unsigned short *qkvTh,*qkvTl,*rnTh,*rnTl,*oTh,*oTl,*w1Th,*w1Tl,*w2Th,*w2Tl,*pTh,*pTl;
    unsigned short *ktTh,*ktTl,*rkTh,*rkTl,*vTh,*vTl,*prTh,*qA0h,*qA0l,*qA1h,*qA1l;
    unsigned short *hAh,*hAl,*mAh,*mAl,*cAh,*cAl,*rAh,*rAl,*avAh,*avAl,*ffAh,*ffAl;
#define SYM(p, s) cudaGetSymbolAddress((void**)&p, s)
    SYM(h,g_h); SYM(r,g_r); SYM(heads,g_heads); SYM(rk,g_rk); SYM(ac,g_ac); SYM(bd,g_bd);
    SYM(av,g_av); SYM(ff,g_ff);
    SYM(qkvTh,g_qkvT_h); SYM(qkvTl,g_qkvT_l); SYM(rnTh,g_rnT_h); SYM(rnTl,g_rnT_l);
    SYM(oTh,g_oT_h); SYM(oTl,g_oT_l); SYM(w1Th,g_w1T_h); SYM(w1Tl,g_w1T_l);
    SYM(w2Th,g_w2T_h); SYM(w2Tl,g_w2T_l); SYM(pTh,g_pT_h); SYM(pTl,g_pT_l);
    SYM(ktTh,g_ktT_h); SYM(ktTl,g_ktT_l); SYM(rkTh,g_rkT_h); SYM(rkTl,g_rkT_l);
    SYM(vTh,g_vT_h); SYM(vTl,g_vT_l); SYM(prTh,g_prT_h);
    SYM(qA0h,g_qA0_h); SYM(qA0l,g_qA0_l); SYM(qA1h,g_qA1_h); SYM(qA1l,g_qA1_l);
    SYM(hAh,g_hA_h); SYM(hAl,g_hA_l); SYM(mAh,g_mA_h); SYM(mAl,g_mA_l);
    SYM(cAh,g_cA_h); SYM(cAl,g_cA_l); SYM(rAh,g_rA_h); SYM(rAl,g_rA_l);
    SYM(avAh,g_avA_h); SYM(avAl,g_avA_l); SYM(ffAh,g_ffA_h); SYM(ffAl,g_ffA_l);
#undef SYM

    pack_wT<<<dim3(18,12,NLAYER),256>>>(qkv_w, TND, 1, (long)DMODEL*TND, 0, DMODEL, TND,
                                        qkvTh, qkvTl, 12, (long)18*12*TUSH);
    embed_kernel<<<(QB*DMODEL+255)/256, 256>>>(x, emb);
    posemb_kernel<<<(KLEN*DMODEL+255)/256, 256>>>();

    int first = 1;
    for (int l = 0; l < NLAYER; l++) {
        long wq = (long)l*18*12*TUSH;
        float* q = heads + (size_t)(CLEN+MLEN)*BSZ*TND;

        // qkv: nt2 (144 CTAs, ~1 wave)
        gemm_tc<<<dim3(9,16,1),256,GT_SMEM_N2>>>(hAh, hAl, 0,0, qkvTh+wq, qkvTl+wq, 0,0,
            q, TND, 0,0, 0,0,0, QB, TND, DMODEL, 0,0,0,1,1);
        if (first) {
            pack_wT<<<dim3(6,12,NLAYER),256>>>(r_net_w, ND, 1, (long)DMODEL*ND, 0, DMODEL, ND,
                                               rnTh, rnTl, 12, (long)6*12*TUSH);
            pack_wT<<<dim3(6,12,NLAYER),256>>>(o_w, DMODEL, 1, (long)ND*DMODEL, 0, ND, DMODEL,
                                               oTh, oTl, 12, (long)6*12*TUSH);
            pack_wT<<<dim3(24,12,NLAYER),256>>>(w1, DFF, 1, (long)DMODEL*DFF, 0, DMODEL, DFF,
                                                w1Th, w1Tl, 12, (long)24*12*TUSH);
            pack_wT<<<dim3(6,48,NLAYER),256>>>(w2, DMODEL, 1, (long)DFF*DMODEL, 0, DFF, DMODEL,
                                               w2Th, w2Tl, 48, (long)6*48*TUSH);
            pack_wT<<<dim3(79,12,1),256>>>(proj_w, NV, 1, 0,0, DMODEL, NV, pTh, pTl, 12, 0);
            pack_nT<<<dim3(1,12,1),256>>>(condition, DMODEL, 1, 0,0, CLEN*BSZ, DMODEL, 0, cAh, cAl, 12, 0);
            pack_nT<<<dim3(9,12,1),256>>>(r, DMODEL, 1, 0,0, KLEN, DMODEL, 0, rAh, rAl, 12, 0);
            first = 0;
        }
        pack_nT<<<dim3(16,12,1),256>>>(mems + (size_t)l*MLEN*BSZ*DMODEL, DMODEL, 1, 0,0,
                                       MLEN*BSZ, DMODEL, 0, mAh, mAl, 12, 0);
        // small GEMMs: nt1 dbuf (more CTAs in flight)
        gemm_tc<<<dim3(12,1,1),256,GT_SMEM_N1>>>(cAh, cAl, 0,0,
            qkvTh+wq+(long)6*12*TUSH, qkvTl+wq+(long)6*12*TUSH, 0,0,
            heads + ND, TND, 0,0, 0,0,0, CLEN*BSZ, 2*ND, DMODEL, 0,0,0,1,0);
        gemm_tc<<<dim3(12,16,1),256,GT_SMEM_N1>>>(mAh, mAl, 0,0,
            qkvTh+wq+(long)6*12*TUSH, qkvTl+wq+(long)6*12*TUSH, 0,0,
            heads + (size_t)CLEN*BSZ*TND + ND, TND, 0,0, 0,0,0, MLEN*BSZ, 2*ND, DMODEL, 0,0,0,1,0);
        gemm_tc<<<dim3(6,9,1),256,GT_SMEM_N1>>>(rAh, rAl, 0,0,
            rnTh+(long)l*6*12*TUSH, rnTl+(long)l*6*12*TUSH, 0,0,
            rk, ND, 0,0, 0,0,0, KLEN, ND, DMODEL, 0,0,0,1,0);

        pack_nT<<<dim3(4,1,NBATCH),256>>>(q, BSZ*TND, NH, TND, DH, QLEN, DH, r_w_bias,
                                          qA0h, qA0l, 1, (long)4*TUSH);
        pack_nT<<<dim3(4,1,NBATCH),256>>>(q, BSZ*TND, NH, TND, DH, QLEN, DH, r_r_bias,
                                          qA1h, qA1l, 1, (long)4*TUSH);
        pack_nT<<<dim3(9,1,NBATCH),256>>>(heads + ND, BSZ*TND, NH, TND, DH, KLEN, DH, 0,
                                          ktTh, ktTl, 1, (long)9*TUSH);
        pack_nT<<<dim3(9,1,12),256>>>(rk, ND, NH, 0, DH, KLEN, DH, 0,
                                      rkTh, rkTl, 1, (long)9*TUSH);
        pack_wT<<<dim3(1,17,NBATCH),256>>>(heads + 2*ND, BSZ*TND, NH, TND, DH, KLEN, DH,
                                           vTh, vTl, 17, (long)17*TUSH);

        gemm_tc<<<dim3(9,4,NBATCH),256,GT_SMEM_SB>>>(qA0h, qA0l, (long)NH*4*TUSH, (long)4*TUSH,
            ktTh, ktTl, (long)NH*9*TUSH, (long)9*TUSH,
            ac, KLEN, (long)NH*QLEN*KLEN, (long)QLEN*KLEN, 0,0,0, QLEN, KLEN, DH, 0,0,2,0,0);
        gemm_tc<<<dim3(9,4,NBATCH),256,GT_SMEM_SB>>>(qA1h, qA1l, (long)NH*4*TUSH, (long)4*TUSH,
            rkTh, rkTl, 0, (long)9*TUSH,
            bd, KLEN, (long)NH*QLEN*KLEN, (long)QLEN*KLEN, 0,0,0, QLEN, KLEN, DH, 0,0,1,0,0);

        softmax_kernel<<<dim3(QLEN,NBATCH),256>>>();

        gemm_tc<<<dim3(1,4,NBATCH),256,GT_SMEM_PV>>>(prTh, 0, (long)NH*4*17*TUSH, (long)4*17*TUSH,
            vTh, vTl, (long)NH*17*TUSH, (long)17*TUSH,
            av, BSZ*DMODEL, DMODEL, DH, 0,0,0, QLEN, DH, KLEN, 0,0,0,1,0);

        pack_nT<<<dim3(16,12,1),256>>>(av, DMODEL, 1, 0,0, QB, DMODEL, 0, avAh, avAl, 12, 0);
        gemm_tc<<<dim3(6,16,1),256,GT_SMEM_N1>>>(avAh, avAl, 0,0,
            oTh+(long)l*6*12*TUSH, oTl+(long)l*6*12*TUSH, 0,0,
            ff, DMODEL, 0,0, 0,0,0, QB, DMODEL, ND, 0,0,0,1,0);
        add_ln_kernel<<<QB,256>>>(h, ff, ln1_g + l*DMODEL, ln1_b + l*DMODEL, hAh, hAl);

        // w1: nt2 (192 CTAs)
        gemm_tc<<<dim3(12,16,1),256,GT_SMEM_N2>>>(hAh, hAl, 0,0,
            w1Th+(long)l*24*12*TUSH, w1Tl+(long)l*24*12*TUSH, 0,0,
            0, 0, 0,0, ffAh, ffAl, 48, QB, DFF, DMODEL, b1 + (size_t)l*DFF, 1,0,1,1);
        gemm_tc<<<dim3(6,16,1),256,GT_SMEM_N1>>>(ffAh, ffAl, 0,0,
            w2Th+(long)l*6*48*TUSH, w2Tl+(long)l*6*48*TUSH, 0,0,
            av, DMODEL, 0,0, 0,0,0, QB, DMODEL, DFF, b2 + (size_t)l*DMODEL, 0,0,1,0);
        add_ln_kernel<<<QB,256>>>(h, av, ln2_g + l*DMODEL, ln2_b + l*DMODEL, hAh, hAl);
    }

    // vocab proj: nt2 (624 CTAs) + nt1 remainder
    gemm_tc<<<dim3(39,16,1),256,GT_SMEM_N2>>>(hAh, hAl, 0,0, pTh, pTl, 0,0,
        out, NV, 0,0, 0,0,0, QB, NV, DMODEL, proj_b, 0,0,1,1);
    gemm_tc<<<dim3(1,16,1),256,GT_SMEM_N1>>>(hAh, hAl, 0,0,
        pTh + (long)78*12*TUSH, pTl + (long)78*12*TUSH, 0,0,
        out + 9984, NV, 0,0, 0,0,0, QB, NV - 9984, DMODEL, proj_b + 9984, 0,0,1,0);
}